// round 7
// baseline (speedup 1.0000x reference)
#include <cuda_runtime.h>
#include <cstdint>

#define KVOL 27
#define CIN  64
#define COUT 64
#define BM   128

// Set by detect_kmap_dtype: 1 if kmap buffer is int64, 0 if int32.
__device__ int g_kmap_is64;

__global__ void detect_kmap_dtype(const unsigned int* __restrict__ km) {
    // int64 little-endian with values < 2^31 -> every odd 32-bit word is 0.
    // int32 -> odd words are random indices, ~never all zero over 64 samples.
    int all_zero = 1;
    #pragma unroll 1
    for (int i = 0; i < 64; ++i) {
        if (km[2 * i + 1] != 0u) { all_zero = 0; break; }
    }
    g_kmap_is64 = all_zero;
}

// round-to-nearest fp32 -> tf32 (result kept in a b32 reg)
__device__ __forceinline__ uint32_t cvt_tf32(float x) {
    uint32_t u;
    asm("cvt.rna.tf32.f32 %0, %1;" : "=r"(u) : "f"(x));
    return u;
}

__device__ __forceinline__ uint4 cvt4(float4 v) {
    uint4 w;
    w.x = cvt_tf32(v.x); w.y = cvt_tf32(v.y);
    w.z = cvt_tf32(v.z); w.w = cvt_tf32(v.w);
    return w;
}

__device__ __forceinline__ void mma_tf32(float c[4], const uint32_t a[4], const uint32_t b[2]) {
    asm volatile(
        "mma.sync.aligned.m16n8k8.row.col.f32.tf32.tf32.f32 "
        "{%0,%1,%2,%3}, {%4,%5,%6,%7}, {%8,%9}, {%0,%1,%2,%3};\n"
        : "+f"(c[0]), "+f"(c[1]), "+f"(c[2]), "+f"(c[3])
        : "r"(a[0]), "r"(a[1]), "r"(a[2]), "r"(a[3]),
          "r"(b[0]), "r"(b[1]));
}

// XOR swizzles: conflict-free for the m16n8k8 fragment access patterns.
// A: bank = (col ^ 4*(row&7)) % 32 across the 32 fragment lanes -> distinct.
__device__ __forceinline__ int a_off(int row, int col) {
    return row * 64 + (col ^ ((row & 7) << 2));
}
// B: bank = (co ^ 8*(ci&3)) % 32 across the 32 fragment lanes -> distinct.
__device__ __forceinline__ int b_off(int ci, int co) {
    return ci * 64 + (co ^ ((ci & 3) << 3));
}

extern __shared__ float dyn_smem[];

__global__ __launch_bounds__(128, 3)
void sparse_conv_tf32(const float* __restrict__ features,
                      const float* __restrict__ wkernel,
                      const long long* __restrict__ kmap64,
                      const int* __restrict__ kmap32,
                      const int* __restrict__ kmask,
                      float* __restrict__ out,
                      int n_pts)
{
    float* As   = dyn_smem;                        // 128*64 words = 32 KB
    float* Bs   = dyn_smem + BM * 64;              //  64*64 words = 16 KB
    int*   sIdx = (int*)(dyn_smem + BM * 64 + 64 * 64);  // 128*27 ints = 13.5 KB

    const int tid  = threadIdx.x;          // 0..127
    const int lane = tid & 31;
    const int warp = tid >> 5;             // 0..3  (M dimension)
    const int m0   = warp * 32;
    const int g    = lane >> 2;            // 0..7
    const int t4   = lane & 3;             // 0..3
    const long long blk0 = (long long)blockIdx.x * BM;
    const int is64 = g_kmap_is64;

    // ---- precompute fused (mask ? idx : -1) for all 128 pts x 27 offsets,
    //      fully coalesced (the per-k stride-27 loads were 32-way uncoalesced) ----
    {
        const long long entry0    = blk0 * KVOL;
        const long long entry_end = (long long)n_pts * KVOL;
        #pragma unroll 1
        for (int j = 0; j < KVOL; ++j) {
            const long long e = entry0 + j * 128 + tid;
            int v = -1;
            if (e < entry_end && kmask[e]) {
                long long idx = is64 ? kmap64[e] : (long long)kmap32[e];
                if (idx < 0 || idx >= n_pts) idx = 0;   // never fault
                v = (int)idx;
            }
            sIdx[j * 128 + tid] = v;
        }
    }
    __syncthreads();

    float acc[2][8][4];
    #pragma unroll
    for (int mi = 0; mi < 2; ++mi)
        #pragma unroll
        for (int ni = 0; ni < 8; ++ni)
            #pragma unroll
            for (int j = 0; j < 4; ++j)
                acc[mi][ni][j] = 0.0f;

    const int sub = tid >> 4;            // 0..7  (row sub-slot for gather)
    const int cb  = (tid & 15) * 4;      // 16 lanes cover one 256B feature row

    #pragma unroll 1
    for (int k = 0; k < KVOL; ++k) {
        // ---- stage W[k] (64x64 fp32 -> tf32) : linear coalesced load,
        //      swizzled store ----
        {
            const float* wsrc = wkernel + k * (CIN * COUT);
            #pragma unroll
            for (int it = 0; it < 8; ++it) {
                const int off = it * 512 + tid * 4;     // linear word offset
                float4 v = *reinterpret_cast<const float4*>(wsrc + off);
                const int ci = off >> 6;
                const int co = off & 63;
                *reinterpret_cast<uint4*>(Bs + b_off(ci, co)) = cvt4(v);
            }
        }
        // ---- cooperative gather: 16 lanes per row (row = 2 cache lines) ----
        {
            #pragma unroll 4
            for (int r = 0; r < 16; ++r) {
                const int row = r * 8 + sub;
                const int idx = sIdx[row * KVOL + k];   // smem broadcast
                uint4 w = make_uint4(0u, 0u, 0u, 0u);
                if (idx >= 0) {
                    float4 v = *reinterpret_cast<const float4*>(
                        features + (long long)idx * CIN + cb);
                    w = cvt4(v);
                }
                *reinterpret_cast<uint4*>(As + a_off(row, cb)) = w;
            }
        }
        __syncthreads();

        // ---- warp tile 32(M) x 64(N), K=64 in 8 slices of 8 ----
        #pragma unroll
        for (int ks = 0; ks < 8; ++ks) {
            const int kb = ks * 8;
            uint32_t a[2][4];
            #pragma unroll
            for (int mi = 0; mi < 2; ++mi) {
                const int row = m0 + mi * 16 + g;
                const int col = kb + t4;
                a[mi][0] = __float_as_uint(As[a_off(row,     col)]);
                a[mi][1] = __float_as_uint(As[a_off(row + 8, col)]);
                a[mi][2] = __float_as_uint(As[a_off(row,     col + 4)]);
                a[mi][3] = __float_as_uint(As[a_off(row + 8, col + 4)]);
            }
            uint32_t b[8][2];
            #pragma unroll
            for (int ni = 0; ni < 8; ++ni) {
                const int kr = kb + t4;
                const int co = ni * 8 + g;
                b[ni][0] = __float_as_uint(Bs[b_off(kr,     co)]);
                b[ni][1] = __float_as_uint(Bs[b_off(kr + 4, co)]);
            }
            #pragma unroll
            for (int mi = 0; mi < 2; ++mi)
                #pragma unroll
                for (int ni = 0; ni < 8; ++ni)
                    mma_tf32(acc[mi][ni], a[mi], b[ni]);
        }
        __syncthreads();
    }

    // ---- epilogue: c frag layout -> out[n, co] (fp32) ----
    #pragma unroll
    for (int mi = 0; mi < 2; ++mi) {
        const long long r0 = blk0 + m0 + mi * 16 + g;
        #pragma unroll
        for (int ni = 0; ni < 8; ++ni) {
            const int col = ni * 8 + t4 * 2;
            if (r0 < n_pts)
                *reinterpret_cast<float2*>(out + r0 * COUT + col) =
                    make_float2(acc[mi][ni][0], acc[mi][ni][1]);
            if (r0 + 8 < n_pts)
                *reinterpret_cast<float2*>(out + (r0 + 8) * COUT + col) =
                    make_float2(acc[mi][ni][2], acc[mi][ni][3]);
        }
    }
}

extern "C" void kernel_launch(void* const* d_in, const int* in_sizes, int n_in,
                              void* d_out, int out_size) {
    const float* features = (const float*)d_in[0];
    const float* wkernel  = (const float*)d_in[1];
    const void*  kmap     = d_in[2];
    const int*   kmask    = (const int*)d_in[3];
    float*       out      = (float*)d_out;

    const int n_pts = in_sizes[0] / CIN;
    const int grid  = (n_pts + BM - 1) / BM;

    const int shbytes = (BM * 64 + 64 * 64) * 4 + BM * KVOL * 4;  // 62,976 B
    cudaFuncSetAttribute(sparse_conv_tf32,
                         cudaFuncAttributeMaxDynamicSharedMemorySize, shbytes);

    detect_kmap_dtype<<<1, 1>>>((const unsigned int*)kmap);
    sparse_conv_tf32<<<grid, 128, shbytes>>>(features, wkernel,
                                             (const long long*)kmap,
                                             (const int*)kmap,
                                             kmask, out, n_pts);
}

// round 8
// speedup vs baseline: 1.8308x; 1.8308x over previous
#include <cuda_runtime.h>
#include <cstdint>

#define KVOL 27
#define CIN  64
#define COUT 64
#define BM   128

// Set by detect_kmap_dtype: 1 if kmap buffer is int64, 0 if int32.
__device__ int g_kmap_is64;

__global__ void detect_kmap_dtype(const unsigned int* __restrict__ km) {
    // int64 little-endian with values < 2^31 -> every odd 32-bit word is 0.
    // int32 -> odd words are random indices, ~never all zero over 64 samples.
    int all_zero = 1;
    #pragma unroll 1
    for (int i = 0; i < 64; ++i) {
        if (km[2 * i + 1] != 0u) { all_zero = 0; break; }
    }
    g_kmap_is64 = all_zero;
}

// round-to-nearest fp32 -> tf32 bits (same numerics as previous rounds)
__device__ __forceinline__ uint32_t cvt_tf32(float x) {
    uint32_t u;
    asm("cvt.rna.tf32.f32 %0, %1;" : "=r"(u) : "f"(x));
    return u;
}

__device__ __forceinline__ void mma_tf32(float c[4], const uint32_t a[4], const uint32_t b[2]) {
    asm volatile(
        "mma.sync.aligned.m16n8k8.row.col.f32.tf32.tf32.f32 "
        "{%0,%1,%2,%3}, {%4,%5,%6,%7}, {%8,%9}, {%0,%1,%2,%3};\n"
        : "+f"(c[0]), "+f"(c[1]), "+f"(c[2]), "+f"(c[3])
        : "r"(a[0]), "r"(a[1]), "r"(a[2]), "r"(a[3]),
          "r"(b[0]), "r"(b[1]));
}

// XOR swizzles: conflict-free for the m16n8k8 fragment access patterns,
// and 16B-alignment-preserving (A XORs word bits [2:5), B bits [3:5)).
__device__ __forceinline__ int a_off(int row, int col) {
    return row * 64 + (col ^ ((row & 7) << 2));
}
__device__ __forceinline__ int b_off(int ci, int co) {
    return ci * 64 + (co ^ ((ci & 3) << 3));
}

// cp.async 16B, L2-only (gather path), zero-fill when sz==0 (masked rows)
__device__ __forceinline__ void cp16_cg_zfill(uint32_t smem, const void* g, int sz) {
    asm volatile("cp.async.cg.shared.global [%0], [%1], 16, %2;\n"
                 :: "r"(smem), "l"(g), "r"(sz) : "memory");
}
// cp.async 16B, L1-cached (weights: hot, reused every k across blocks)
__device__ __forceinline__ void cp16_ca(uint32_t smem, const void* g) {
    asm volatile("cp.async.ca.shared.global [%0], [%1], 16;\n"
                 :: "r"(smem), "l"(g) : "memory");
}

extern __shared__ float dyn_smem[];

__global__ __launch_bounds__(128, 2)
void sparse_conv_tf32(const float* __restrict__ features,
                      const float* __restrict__ wkernel,
                      const long long* __restrict__ kmap64,
                      const int* __restrict__ kmap32,
                      const int* __restrict__ kmask,
                      float* __restrict__ out,
                      int n_pts)
{
    // [ A0 | A1 | B0 | B1 | sIdx ]  = 64KB + 32KB + 13.5KB = 112.1 KB -> 2 CTA/SM
    float* As   = dyn_smem;                          // 2 x 128*64
    float* Bs   = dyn_smem + 2 * BM * 64;            // 2 x 64*64
    int*   sIdx = (int*)(dyn_smem + 2 * BM * 64 + 2 * 64 * 64);

    const int tid  = threadIdx.x;          // 0..127
    const int lane = tid & 31;
    const int warp = tid >> 5;             // 0..3  (M dimension)
    const int m0   = warp * 32;
    const int g    = lane >> 2;            // 0..7
    const int t4   = lane & 3;             // 0..3
    const long long blk0 = (long long)blockIdx.x * BM;
    const int is64 = g_kmap_is64;

    // ---- fused (mask ? idx : -1) for all 128 pts x 27 offsets, coalesced ----
    {
        const long long entry0    = blk0 * KVOL;
        const long long entry_end = (long long)n_pts * KVOL;
        #pragma unroll 1
        for (int j = 0; j < KVOL; ++j) {
            const long long e = entry0 + j * 128 + tid;
            int v = -1;
            if (e < entry_end && kmask[e]) {
                long long idx = is64 ? kmap64[e] : (long long)kmap32[e];
                if (idx < 0 || idx >= n_pts) idx = 0;   // never fault
                v = (int)idx;
            }
            sIdx[j * 128 + tid] = v;
        }
    }
    __syncthreads();

    const uint32_t as_base = (uint32_t)__cvta_generic_to_shared(As);
    const uint32_t bs_base = (uint32_t)__cvta_generic_to_shared(Bs);

    const int sub = tid >> 4;            // 0..7  (row sub-slot for gather)
    const int cb  = (tid & 15) * 4;      // 16 lanes cover one 256B feature row

    // issue all async loads for kernel-offset k into buffer `buf`
    auto issue = [&](int k, int buf) {
        // B: 64x64 fp32, linear-coalesced 16B chunks, swizzled dst
        const float*   wsrc  = wkernel + k * (CIN * COUT);
        const uint32_t bbase = bs_base + buf * (64 * 64 * 4);
        #pragma unroll
        for (int it = 0; it < 8; ++it) {
            const int off = it * 512 + tid * 4;          // linear word offset
            cp16_ca(bbase + (uint32_t)b_off(off >> 6, off & 63) * 4, wsrc + off);
        }
        // A: 128 rows, 16 lanes/row (256B row = 2 lines), zfill when masked
        const uint32_t abase = as_base + buf * (BM * 64 * 4);
        int idxs[16];
        #pragma unroll
        for (int r = 0; r < 16; ++r)
            idxs[r] = sIdx[(r * 8 + sub) * KVOL + k];    // smem broadcast
        #pragma unroll
        for (int r = 0; r < 16; ++r) {
            const int row = r * 8 + sub;
            const int v   = idxs[r];
            const long long i = (v >= 0) ? (long long)v : 0;
            const int sz  = (v >= 0) ? 16 : 0;
            cp16_cg_zfill(abase + (uint32_t)a_off(row, cb) * 4,
                          features + i * CIN + cb, sz);
        }
        asm volatile("cp.async.commit_group;\n" ::: "memory");
    };

    float acc[2][8][4];
    #pragma unroll
    for (int mi = 0; mi < 2; ++mi)
        #pragma unroll
        for (int ni = 0; ni < 8; ++ni)
            #pragma unroll
            for (int j = 0; j < 4; ++j)
                acc[mi][ni][j] = 0.0f;

    issue(0, 0);   // prologue

    #pragma unroll 1
    for (int k = 0; k < KVOL; ++k) {
        const int cur = k & 1;
        if (k + 1 < KVOL) {
            issue(k + 1, (k + 1) & 1);                       // overlap with mma(k)
            asm volatile("cp.async.wait_group 1;\n" ::: "memory");
        } else {
            asm volatile("cp.async.wait_group 0;\n" ::: "memory");
        }
        __syncthreads();   // buffer `cur` complete across all threads

        const float* A = As + cur * (BM * 64);
        const float* B = Bs + cur * (64 * 64);

        // ---- warp tile 32(M) x 64(N), K=64 in 8 slices of 8; cvt at load ----
        #pragma unroll
        for (int ks = 0; ks < 8; ++ks) {
            const int kb = ks * 8;
            uint32_t a[2][4];
            #pragma unroll
            for (int mi = 0; mi < 2; ++mi) {
                const int row = m0 + mi * 16 + g;
                const int col = kb + t4;
                a[mi][0] = cvt_tf32(A[a_off(row,     col)]);
                a[mi][1] = cvt_tf32(A[a_off(row + 8, col)]);
                a[mi][2] = cvt_tf32(A[a_off(row,     col + 4)]);
                a[mi][3] = cvt_tf32(A[a_off(row + 8, col + 4)]);
            }
            uint32_t b[8][2];
            #pragma unroll
            for (int ni = 0; ni < 8; ++ni) {
                const int kr = kb + t4;
                const int co = ni * 8 + g;
                b[ni][0] = cvt_tf32(B[b_off(kr,     co)]);
                b[ni][1] = cvt_tf32(B[b_off(kr + 4, co)]);
            }
            #pragma unroll
            for (int mi = 0; mi < 2; ++mi)
                #pragma unroll
                for (int ni = 0; ni < 8; ++ni)
                    mma_tf32(acc[mi][ni], a[mi], b[ni]);
        }
        __syncthreads();   // protect `cur` before it is re-issued at k+2
    }

    // ---- epilogue: c frag layout -> out[n, co] (fp32) ----
    #pragma unroll
    for (int mi = 0; mi < 2; ++mi) {
        const long long r0 = blk0 + m0 + mi * 16 + g;
        #pragma unroll
        for (int ni = 0; ni < 8; ++ni) {
            const int col = ni * 8 + t4 * 2;
            if (r0 < n_pts)
                *reinterpret_cast<float2*>(out + r0 * COUT + col) =
                    make_float2(acc[mi][ni][0], acc[mi][ni][1]);
            if (r0 + 8 < n_pts)
                *reinterpret_cast<float2*>(out + (r0 + 8) * COUT + col) =
                    make_float2(acc[mi][ni][2], acc[mi][ni][3]);
        }
    }
}

extern "C" void kernel_launch(void* const* d_in, const int* in_sizes, int n_in,
                              void* d_out, int out_size) {
    const float* features = (const float*)d_in[0];
    const float* wkernel  = (const float*)d_in[1];
    const void*  kmap     = d_in[2];
    const int*   kmask    = (const int*)d_in[3];
    float*       out      = (float*)d_out;

    const int n_pts = in_sizes[0] / CIN;
    const int grid  = (n_pts + BM - 1) / BM;

    const int shbytes = (2 * BM * 64 + 2 * 64 * 64) * 4 + BM * KVOL * 4; // 112,128 B
    cudaFuncSetAttribute(sparse_conv_tf32,
                         cudaFuncAttributeMaxDynamicSharedMemorySize, shbytes);

    detect_kmap_dtype<<<1, 1>>>((const unsigned int*)kmap);
    sparse_conv_tf32<<<grid, 128, shbytes>>>(features, wkernel,
                                             (const long long*)kmap,
                                             (const int*)kmap,
                                             kmask, out, n_pts);
}

// round 10
// speedup vs baseline: 2.9598x; 1.6166x over previous
#include <cuda_runtime.h>
#include <cstdint>

#define KVOL 27
#define CIN  64
#define COUT 64
#define BM   128

// Set by detect_kmap_dtype: 1 if kmap buffer is int64, 0 if int32.
__device__ int g_kmap_is64;
// Pre-converted tf32(rna) image of W in fragment-pair layout (see prep_B):
// per k: 256 rows (row = co*4 + t4) x 16 words. 27 * 16KB = 442 KB.
__device__ unsigned int g_Bimg[KVOL * CIN * COUT];

__global__ void detect_kmap_dtype(const unsigned int* __restrict__ km) {
    // int64 little-endian values < 2^31 -> odd 32-bit words all zero.
    // int32 -> odd words are random indices, ~never all zero over 64 samples.
    int all_zero = 1;
    #pragma unroll 1
    for (int i = 0; i < 64; ++i)
        if (km[2 * i + 1] != 0u) { all_zero = 0; break; }
    g_kmap_is64 = all_zero;
}

// Fragment-pair B layout:
//   value W[k][ci][co] -> row = co*4 + (ci&3), pair word w = 2*(ci>>3) + ((ci>>2)&1)
//   stored at word row*16 + ((w + 2*((row>>1)&7)) & 15)   (even rotation: pairs
//   stay adjacent; rotation makes each 16-lane LDS.64 phase bank-conflict-free).
// Fragment read (lane g=lane>>2, t4=lane&3, tile col block ni, k-slice ks):
//   row = (ni*8+g)*4 + t4 ; one LDS.64 at word row*16 + ((2*ks + rot)&15)
//   yields b0 = W^T[co][8ks+t4], b1 = W^T[co][8ks+4+t4] -- exactly the
//   m16n8k8 B fragment pair.
__global__ void prep_B(const float* __restrict__ wk) {
    const int k = blockIdx.x;
    for (int i = threadIdx.x; i < CIN * COUT; i += blockDim.x) {
        const int ci = i >> 6;
        const int co = i & 63;
        uint32_t t;
        asm("cvt.rna.tf32.f32 %0, %1;" : "=r"(t) : "f"(wk[k * 4096 + i]));
        const int row = co * 4 + (ci & 3);
        const int w   = 2 * (ci >> 3) + ((ci >> 2) & 1);
        const int rot = 2 * ((row >> 1) & 7);
        g_Bimg[k * 4096 + row * 16 + ((w + rot) & 15)] = t;
    }
}

__device__ __forceinline__ void mma_tf32(float c[4], const uint32_t a[4], const uint32_t b[2]) {
    asm volatile(
        "mma.sync.aligned.m16n8k8.row.col.f32.tf32.tf32.f32 "
        "{%0,%1,%2,%3}, {%4,%5,%6,%7}, {%8,%9}, {%0,%1,%2,%3};\n"
        : "+f"(c[0]), "+f"(c[1]), "+f"(c[2]), "+f"(c[3])
        : "r"(a[0]), "r"(a[1]), "r"(a[2]), "r"(a[3]),
          "r"(b[0]), "r"(b[1]));
}

// A XOR swizzle: conflict-free fragment reads, 16B-alignment-preserving.
__device__ __forceinline__ int a_off(int row, int col) {
    return row * 64 + (col ^ ((row & 7) << 2));
}

// cp.async 16B, L2-only (gather), zero-fill when sz==0 (masked rows)
__device__ __forceinline__ void cp16_cg_zfill(uint32_t smem, const void* g, int sz) {
    asm volatile("cp.async.cg.shared.global [%0], [%1], 16, %2;\n"
                 :: "r"(smem), "l"(g), "r"(sz) : "memory");
}
// cp.async 16B, L1-cached (weight image: hot across blocks)
__device__ __forceinline__ void cp16_ca(uint32_t smem, const void* g) {
    asm volatile("cp.async.ca.shared.global [%0], [%1], 16;\n"
                 :: "r"(smem), "l"(g) : "memory");
}

extern __shared__ float dyn_smem[];

// [ A0 | A1 | B0 | B1 | sIdx ] = 64KB + 32KB + 13.5KB = 112.1KB -> 2 CTA/SM
#define A_WORDS   (BM * 64)
#define B_WORDS   (64 * 64)

__global__ __launch_bounds__(128, 2)
void sparse_conv_tf32(const float* __restrict__ features,
                      const long long* __restrict__ kmap64,
                      const int* __restrict__ kmap32,
                      const int* __restrict__ kmask,
                      float* __restrict__ out,
                      int n_pts)
{
    float* As   = dyn_smem;                          // 2 x 128*64
    float* Bs   = dyn_smem + 2 * A_WORDS;            // 2 x 64*64 (pair layout)
    int*   sIdx = (int*)(dyn_smem + 2 * A_WORDS + 2 * B_WORDS);

    const int tid  = threadIdx.x;          // 0..127
    const int lane = tid & 31;
    const int warp = tid >> 5;             // 0..3  (M dimension)
    const int m0   = warp * 32;
    const int g    = lane >> 2;            // 0..7
    const int t4   = lane & 3;             // 0..3
    const long long blk0 = (long long)blockIdx.x * BM;
    const int is64 = g_kmap_is64;

    // ---- fused (mask ? idx : -1) for all 128 pts x 27 offsets, coalesced ----
    {
        const long long entry0    = blk0 * KVOL;
        const long long entry_end = (long long)n_pts * KVOL;
        #pragma unroll 1
        for (int j = 0; j < KVOL; ++j) {
            const long long e = entry0 + j * 128 + tid;
            int v = -1;
            if (e < entry_end && kmask[e]) {
                long long idx = is64 ? kmap64[e] : (long long)kmap32[e];
                if (idx < 0 || idx >= n_pts) idx = 0;   // never fault
                v = (int)idx;
            }
            sIdx[j * 128 + tid] = v;
        }
    }
    __syncthreads();

    const uint32_t as_base = (uint32_t)__cvta_generic_to_shared(As);
    const uint32_t bs_base = (uint32_t)__cvta_generic_to_shared(Bs);

    const int sub = tid >> 4;            // 0..7  (row sub-slot for gather)
    const int cb  = (tid & 15) * 4;      // 16 lanes cover one 256B feature row

    // issue all async loads for kernel-offset k into buffer `buf`
    auto issue = [&](int k, int buf) {
        // B: straight 16KB copy of the prepped image (8 x 16B chunks / thread)
        const unsigned int* bsrc  = g_Bimg + k * 4096;
        const uint32_t      bbase = bs_base + buf * (B_WORDS * 4);
        #pragma unroll
        for (int it = 0; it < 8; ++it)
            cp16_ca(bbase + it * 2048 + tid * 16, bsrc + it * 512 + tid * 4);
        // A: 128 rows, 16 lanes/row (256B row = 2 lines), zfill when masked
        const uint32_t abase = as_base + buf * (A_WORDS * 4);
        int idxs[16];
        #pragma unroll
        for (int r = 0; r < 16; ++r)
            idxs[r] = sIdx[(r * 8 + sub) * KVOL + k];    // smem broadcast
        #pragma unroll
        for (int r = 0; r < 16; ++r) {
            const int row = r * 8 + sub;
            const int v   = idxs[r];
            const long long i = (v >= 0) ? (long long)v : 0;
            cp16_cg_zfill(abase + (uint32_t)a_off(row, cb) * 4,
                          features + i * CIN + cb, (v >= 0) ? 16 : 0);
        }
        asm volatile("cp.async.commit_group;\n" ::: "memory");
    };

    float acc[2][8][4];
    #pragma unroll
    for (int mi = 0; mi < 2; ++mi)
        #pragma unroll
        for (int ni = 0; ni < 8; ++ni)
            #pragma unroll
            for (int j = 0; j < 4; ++j)
                acc[mi][ni][j] = 0.0f;

    issue(0, 0);   // prologue

    // B fragment addressing pieces (rotation is ni-invariant: ni*32 ≡ 0 mod 16)
    const int row0  = g * 4 + t4;                 // 0..31
    const int rot   = 2 * ((row0 >> 1) & 7);

    #pragma unroll 1
    for (int k = 0; k < KVOL; ++k) {
        const int cur = k & 1;
        if (k + 1 < KVOL) {
            issue(k + 1, (k + 1) & 1);                       // overlap with mma(k)
            asm volatile("cp.async.wait_group 1;\n" ::: "memory");
        } else {
            asm volatile("cp.async.wait_group 0;\n" ::: "memory");
        }
        __syncthreads();   // buffer `cur` complete across all threads

        const float* A  = As + cur * A_WORDS;
        const float* Bp = Bs + cur * B_WORDS;

        // ---- warp tile 32(M) x 64(N), K=64 in 8 slices of 8 ----
        #pragma unroll
        for (int ks = 0; ks < 8; ++ks) {
            const int kb = ks * 8;
            const int wp = (2 * ks + rot) & 15;   // pair word within B row
            uint32_t a[2][4];
            #pragma unroll
            for (int mi = 0; mi < 2; ++mi) {
                const int row = m0 + mi * 16 + g;
                const int col = kb + t4;
                a[mi][0] = __float_as_uint(A[a_off(row,     col)]);
                a[mi][1] = __float_as_uint(A[a_off(row + 8, col)]);
                a[mi][2] = __float_as_uint(A[a_off(row,     col + 4)]);
                a[mi][3] = __float_as_uint(A[a_off(row + 8, col + 4)]);
            }
            uint32_t b[8][2];
            #pragma unroll
            for (int ni = 0; ni < 8; ++ni) {
                const uint2 pv = *reinterpret_cast<const uint2*>(
                    Bp + (ni * 32 + row0) * 16 + wp);
                b[ni][0] = pv.x;
                b[ni][1] = pv.y;
            }
            #pragma unroll
            for (int mi = 0; mi < 2; ++mi)
                #pragma unroll
                for (int ni = 0; ni < 8; ++ni)
                    mma_tf32(acc[mi][ni], a[mi], b[ni]);
        }
        __syncthreads();   // protect `cur` before it is re-issued at k+2
    }

    // ---- epilogue: c frag layout -> out[n, co] (fp32) ----
    #pragma unroll
    for (int mi = 0; mi < 2; ++mi) {
        const long long r0 = blk0 + m0 + mi * 16 + g;
        #pragma unroll
        for (int ni = 0; ni < 8; ++ni) {
            const int col = ni * 8 + t4 * 2;
            if (r0 < n_pts)
                *reinterpret_cast<float2*>(out + r0 * COUT + col) =
                    make_float2(acc[mi][ni][0], acc[mi][ni][1]);
            if (r0 + 8 < n_pts)
                *reinterpret_cast<float2*>(out + (r0 + 8) * COUT + col) =
                    make_float2(acc[mi][ni][2], acc[mi][ni][3]);
        }
    }
}

extern "C" void kernel_launch(void* const* d_in, const int* in_sizes, int n_in,
                              void* d_out, int out_size) {
    const float* features = (const float*)d_in[0];
    const float* wkernel  = (const float*)d_in[1];
    const void*  kmap     = d_in[2];
    const int*   kmask    = (const int*)d_in[3];
    float*       out      = (float*)d_out;

    const int n_pts = in_sizes[0] / CIN;
    const int grid  = (n_pts + BM - 1) / BM;

    const int shbytes = (2 * A_WORDS + 2 * B_WORDS) * 4 + BM * KVOL * 4; // 112,128 B
    cudaFuncSetAttribute(sparse_conv_tf32,
                         cudaFuncAttributeMaxDynamicSharedMemorySize, shbytes);

    detect_kmap_dtype<<<1, 1>>>((const unsigned int*)kmap);
    prep_B<<<KVOL, 128>>>(wkernel);
    sparse_conv_tf32<<<grid, 128, shbytes>>>(features,
                                             (const long long*)kmap,
                                             (const int*)kmap,
                                             kmask, out, n_pts);
}

// round 11
// speedup vs baseline: 4.9072x; 1.6580x over previous
#include <cuda_runtime.h>
#include <cuda_fp16.h>
#include <cstdint>

#define KVOL 27
#define CIN  64
#define COUT 64
#define BM   128
#define FEAT_CAP 67108864LL   // halves (128 MiB static image)

__device__ int g_kmap_is64;
// fp16(rna) W image in fragment-pair layout (see prep_B): per k, 4 k-slice
// planes of 256 rows x 4 halves. 27 * 8KB = 216 KB.
__device__ unsigned short g_Bimg[KVOL * CIN * COUT];
// fp16(rna) image of features, rebuilt every launch by prep_feat.
__device__ __half g_feat[FEAT_CAP];

__global__ void detect_kmap_dtype(const unsigned int* __restrict__ km) {
    // int64 little-endian values < 2^31 -> odd 32-bit words all zero.
    // int32 -> odd words are random indices, ~never all zero over 64 samples.
    int all_zero = 1;
    #pragma unroll 1
    for (int i = 0; i < 64; ++i)
        if (km[2 * i + 1] != 0u) { all_zero = 0; break; }
    g_kmap_is64 = all_zero;
}

__global__ void prep_feat(const float* __restrict__ f, long long n) {
    long long i = ((long long)blockIdx.x * blockDim.x + threadIdx.x) * 8;
    if (i + 8 <= n) {
        float4 v0 = *reinterpret_cast<const float4*>(f + i);
        float4 v1 = *reinterpret_cast<const float4*>(f + i + 4);
        __half2 h0 = __floats2half2_rn(v0.x, v0.y);
        __half2 h1 = __floats2half2_rn(v0.z, v0.w);
        __half2 h2 = __floats2half2_rn(v1.x, v1.y);
        __half2 h3 = __floats2half2_rn(v1.z, v1.w);
        uint4 o;
        o.x = *reinterpret_cast<unsigned*>(&h0);
        o.y = *reinterpret_cast<unsigned*>(&h1);
        o.z = *reinterpret_cast<unsigned*>(&h2);
        o.w = *reinterpret_cast<unsigned*>(&h3);
        *reinterpret_cast<uint4*>(&g_feat[i]) = o;
    } else {
        for (; i < n && i < FEAT_CAP; ++i) g_feat[i] = __float2half_rn(f[i]);
    }
}

// Fragment-pair B layout for mma.m16n8k16.row.col fp16:
//   B fragment of thread (g=lane>>2, t4=lane&3), col n=co, k-slice ks needs
//   halves { W[k][16ks+2t4][co], [16ks+2t4+1], [16ks+2t4+8], [16ks+2t4+9] }.
//   Store them as one 8-byte word at plane ks (2KB), row = co*4 + t4.
//   Bank check: rows read per 16-lane LDS.64 phase are 16 consecutive ->
//   byte stride 8 -> banks {0,2,..,30}, conflict-free with no rotation.
__global__ void prep_B(const float* __restrict__ wk) {
    const int k = blockIdx.x;
    for (int i = threadIdx.x; i < CIN * COUT; i += blockDim.x) {
        const int ci = i >> 6;
        const int co = i & 63;
        const unsigned short h =
            __half_as_ushort(__float2half_rn(wk[k * 4096 + i]));
        const int ks = ci >> 4;
        const int kk = ci & 15;
        const int t4 = (kk & 7) >> 1;
        const int hi = ((kk >> 3) << 1) | (kk & 1);   // half slot in the word
        g_Bimg[k * 4096 + (ks * 256 + co * 4 + t4) * 4 + hi] = h;
    }
}

__device__ __forceinline__ void mma_f16(float c[4], const uint32_t a[4], const uint32_t b[2]) {
    asm volatile(
        "mma.sync.aligned.m16n8k16.row.col.f32.f16.f16.f32 "
        "{%0,%1,%2,%3}, {%4,%5,%6,%7}, {%8,%9}, {%0,%1,%2,%3};\n"
        : "+f"(c[0]), "+f"(c[1]), "+f"(c[2]), "+f"(c[3])
        : "r"(a[0]), "r"(a[1]), "r"(a[2]), "r"(a[3]),
          "r"(b[0]), "r"(b[1]));
}

__device__ __forceinline__ void ldsm_x4(uint32_t a[4], uint32_t addr) {
    asm volatile("ldmatrix.sync.aligned.m8n8.x4.shared.b16 {%0,%1,%2,%3}, [%4];"
                 : "=r"(a[0]), "=r"(a[1]), "=r"(a[2]), "=r"(a[3]) : "r"(addr));
}

// cp.async 16B, L2-only (gather), zero-fill when sz==0 (masked rows)
__device__ __forceinline__ void cp16_cg_zfill(uint32_t smem, const void* g, int sz) {
    asm volatile("cp.async.cg.shared.global [%0], [%1], 16, %2;\n"
                 :: "r"(smem), "l"(g), "r"(sz) : "memory");
}
// cp.async 16B, L1-cached (weight image: hot across blocks)
__device__ __forceinline__ void cp16_ca(uint32_t smem, const void* g) {
    asm volatile("cp.async.ca.shared.global [%0], [%1], 16;\n"
                 :: "r"(smem), "l"(g) : "memory");
}

extern __shared__ char dyn_smem[];

// SMEM layout (bytes): A bufs 2x16KB @0, B bufs 2x8KB @32768, sIdx @49152.
#define A_BYTES   16384
#define B_BYTES   8192
#define OFF_B     32768
#define OFF_IDX   49152
#define SMEM_TOTAL (OFF_IDX + BM * KVOL * 4)   // 62,976 B -> 3 CTA/SM

__global__ __launch_bounds__(128, 3)
void sparse_conv_f16(const long long* __restrict__ kmap64,
                     const int* __restrict__ kmap32,
                     const int* __restrict__ kmask,
                     float* __restrict__ out,
                     int n_pts)
{
    int* sIdx = (int*)(dyn_smem + OFF_IDX);
    const uint32_t sbase = (uint32_t)__cvta_generic_to_shared(dyn_smem);

    const int tid  = threadIdx.x;          // 0..127
    const int lane = tid & 31;
    const int warp = tid >> 5;             // 0..3  (M dimension)
    const int m0   = warp * 32;
    const int g    = lane >> 2;            // 0..7
    const int t4   = lane & 3;             // 0..3
    const long long blk0 = (long long)blockIdx.x * BM;
    const int is64 = g_kmap_is64;

    // ---- fused (mask ? idx : -1) for all 128 pts x 27 offsets, coalesced ----
    {
        const long long entry0    = blk0 * KVOL;
        const long long entry_end = (long long)n_pts * KVOL;
        #pragma unroll 1
        for (int j = 0; j < KVOL; ++j) {
            const long long e = entry0 + j * 128 + tid;
            int v = -1;
            if (e < entry_end && kmask[e]) {
                long long idx = is64 ? kmap64[e] : (long long)kmap32[e];
                if (idx < 0 || idx >= n_pts) idx = 0;   // never fault
                v = (int)idx;
            }
            sIdx[j * 128 + tid] = v;
        }
    }
    __syncthreads();

    // gather assignment: 8 lanes cover one 128B fp16 feature row (1 line)
    const int chunk  = tid & 7;            // 16B chunk within row
    const int rowgrp = tid >> 3;           // 0..15

    auto issue = [&](int k, int buf) {
        // B: 8KB copy of the prepped image (4 x 16B per thread)
        const unsigned short* bsrc = g_Bimg + k * 4096;
        const uint32_t bb = sbase + OFF_B + buf * B_BYTES;
        #pragma unroll
        for (int it = 0; it < 4; ++it)
            cp16_ca(bb + it * 2048 + tid * 16, bsrc + it * 1024 + tid * 8);
        // A: 128 rows x 128B, chunk-swizzled (c ^ (row&7)), zfill masked
        const uint32_t ab = sbase + buf * A_BYTES;
        int idxs[8];
        #pragma unroll
        for (int r = 0; r < 8; ++r)
            idxs[r] = sIdx[(r * 16 + rowgrp) * KVOL + k];   // broadcast
        #pragma unroll
        for (int r = 0; r < 8; ++r) {
            const int row = r * 16 + rowgrp;
            const int v   = idxs[r];
            const long long i = (v >= 0) ? (long long)v : 0;
            cp16_cg_zfill(ab + row * 128 + ((chunk ^ (row & 7)) << 4),
                          g_feat + i * CIN + chunk * 8, (v >= 0) ? 16 : 0);
        }
        asm volatile("cp.async.commit_group;\n" ::: "memory");
    };

    float acc[2][8][4];
    #pragma unroll
    for (int mi = 0; mi < 2; ++mi)
        #pragma unroll
        for (int ni = 0; ni < 8; ++ni)
            #pragma unroll
            for (int j = 0; j < 4; ++j)
                acc[mi][ni][j] = 0.0f;

    issue(0, 0);   // prologue

    // ldmatrix lane addressing: lanes 0-7 -> matrix0 (rows 0-7, chunk 2ks),
    // 8-15 -> rows 8-15, 16-23 -> rows 0-7 chunk 2ks+1, 24-31 -> rows 8-15.
    const int ldrow   = (lane & 7) + 8 * ((lane >> 3) & 1);
    const int ldcoff  = lane >> 4;                  // 0 or 1
    const int brow    = g * 4 + t4;                 // B row base (ni=0)

    #pragma unroll 1
    for (int k = 0; k < KVOL; ++k) {
        const int cur = k & 1;
        if (k + 1 < KVOL) {
            issue(k + 1, (k + 1) & 1);                       // overlap with mma(k)
            asm volatile("cp.async.wait_group 1;\n" ::: "memory");
        } else {
            asm volatile("cp.async.wait_group 0;\n" ::: "memory");
        }
        __syncthreads();   // buffer `cur` complete across all threads

        const uint32_t a_sm = sbase + cur * A_BYTES;
        const char*    Bp   = dyn_smem + OFF_B + cur * B_BYTES;

        // ---- warp tile 32(M) x 64(N), K=64 in 4 slices of 16 ----
        #pragma unroll
        for (int ks = 0; ks < 4; ++ks) {
            uint32_t a[2][4];
            #pragma unroll
            for (int mi = 0; mi < 2; ++mi) {
                const int row = m0 + mi * 16 + ldrow;
                ldsm_x4(a[mi], a_sm + row * 128 +
                               (((2 * ks + ldcoff) ^ (row & 7)) << 4));
            }
            uint32_t b[8][2];
            #pragma unroll
            for (int ni = 0; ni < 8; ++ni) {
                const uint2 pv = *reinterpret_cast<const uint2*>(
                    Bp + ks * 2048 + (ni * 32 + brow) * 8);
                b[ni][0] = pv.x;
                b[ni][1] = pv.y;
            }
            #pragma unroll
            for (int mi = 0; mi < 2; ++mi)
                #pragma unroll
                for (int ni = 0; ni < 8; ++ni)
                    mma_f16(acc[mi][ni], a[mi], b[ni]);
        }
        __syncthreads();   // protect `cur` before it is re-issued at k+2
    }

    // ---- epilogue: c frag layout -> out[n, co] (fp32) ----
    #pragma unroll
    for (int mi = 0; mi < 2; ++mi) {
        const long long r0 = blk0 + m0 + mi * 16 + g;
        #pragma unroll
        for (int ni = 0; ni < 8; ++ni) {
            const int col = ni * 8 + t4 * 2;
            if (r0 < n_pts)
                *reinterpret_cast<float2*>(out + r0 * COUT + col) =
                    make_float2(acc[mi][ni][0], acc[mi][ni][1]);
            if (r0 + 8 < n_pts)
                *reinterpret_cast<float2*>(out + (r0 + 8) * COUT + col) =
                    make_float2(acc[mi][ni][2], acc[mi][ni][3]);
        }
    }
}

extern "C" void kernel_launch(void* const* d_in, const int* in_sizes, int n_in,
                              void* d_out, int out_size) {
    const float* features = (const float*)d_in[0];
    const float* wkernel  = (const float*)d_in[1];
    const void*  kmap     = d_in[2];
    const int*   kmask    = (const int*)d_in[3];
    float*       out      = (float*)d_out;

    long long nfeat = (long long)in_sizes[0];
    if (nfeat > FEAT_CAP) nfeat = FEAT_CAP;          // defensive
    int n_pts = (int)(nfeat / CIN);
    const int grid = (n_pts + BM - 1) / BM;

    cudaFuncSetAttribute(sparse_conv_f16,
                         cudaFuncAttributeMaxDynamicSharedMemorySize, SMEM_TOTAL);

    detect_kmap_dtype<<<1, 1>>>((const unsigned int*)kmap);
    prep_feat<<<(int)((nfeat / 8 + 255) / 256), 256>>>(features, nfeat);
    prep_B<<<KVOL, 128>>>(wkernel);
    sparse_conv_f16<<<grid, 128, SMEM_TOTAL>>>((const long long*)kmap,
                                               (const int*)kmap,
                                               kmask, out, n_pts);
}